// round 14
// baseline (speedup 1.0000x reference)
#include <cuda_runtime.h>
#include <cuda_fp16.h>
#include <cstdint>
#include <cfloat>

#define D       256
#define KMAX    1024
#define NMAX    65536
#define BM      128
#define ESTR    264     // fp16 stride for e smem tile
#define WSTR    72      // fp16 stride for w smem chunks
#define DCH     64
#define RESCUE_THRESH 1.5e-4f
#define CAND_WINDOW   2.5e-4f

// -------- device scratch (static; no runtime allocation) --------
__device__ __half       g_eh[(size_t)NMAX * D];
__device__ __half       g_wh[(size_t)KMAX * D];
__device__ float        g_nw[KMAX];
__device__ float        g_A[NMAX];
__device__ float        g_bestS[NMAX];
__device__ unsigned long long g_rbest[NMAX];
__device__ int          g_idx[NMAX];
__device__ unsigned int g_counts[KMAX];
__device__ double       g_loss;
__device__ int          g_flagcnt;
__device__ int          g_flaglist[NMAX];

// smem (argmin): e + 3 w buffers + misc
#define SM_E_B     (BM * ESTR * 2)             // 67584
#define SM_WBUF_B  (3 * BM * WSTR * 2)         // 55296
#define SMEM_BYTES (SM_E_B + SM_WBUF_B + BM * 4 + KMAX * 4 \
                    + BM * 2 * 4 + BM * 2 * 4 + BM * 2 * 4)
// smem (candidate): e + 3 w buffers + A + nw(256) + bestS + rows
#define CAND_SMEM_BYTES (SM_E_B + SM_WBUF_B + BM * 4 + 256 * 4 + BM * 4 + BM * 4)

// ---------------------------------------------------------------------------
// helpers
// ---------------------------------------------------------------------------
__device__ __forceinline__ void cpa16(void* dst, const void* src) {
    unsigned d = (unsigned)__cvta_generic_to_shared(dst);
    asm volatile("cp.async.cg.shared.global [%0], [%1], 16;\n" :: "r"(d), "l"(src));
}
__device__ __forceinline__ void cpa_commit() {
    asm volatile("cp.async.commit_group;\n");
}
__device__ __forceinline__ void cpa_wait0() {
    asm volatile("cp.async.wait_group 0;\n");
}
__device__ __forceinline__ void cpa_wait1() {
    asm volatile("cp.async.wait_group 1;\n");
}
__device__ __forceinline__ void mma_f16(float* c, const unsigned* a, unsigned b0, unsigned b1) {
    asm volatile(
        "mma.sync.aligned.m16n8k16.row.col.f32.f16.f16.f32 "
        "{%0,%1,%2,%3}, {%4,%5,%6,%7}, {%8,%9}, {%0,%1,%2,%3};\n"
        : "+f"(c[0]), "+f"(c[1]), "+f"(c[2]), "+f"(c[3])
        : "r"(a[0]), "r"(a[1]), "r"(a[2]), "r"(a[3]), "r"(b0), "r"(b1));
}

// exact fp32 re-score of one (row, code); summation order matches the
// previously-validated rescue path (4 accumulators + tree).
__device__ __forceinline__ void exact_rescore(const float* __restrict__ e,
                                              const float* __restrict__ w,
                                              int row, int code) {
    const float4* ep = (const float4*)(e + (size_t)row * D);
    const float4* wp = (const float4*)(w + (size_t)code * D);
    float a0 = 0.f, a1 = 0.f, a2 = 0.f, a3 = 0.f;
    #pragma unroll
    for (int v = 0; v < 64; v += 2) {
        float4 e0 = __ldg(ep + v), e1 = __ldg(ep + v + 1);
        float4 w0 = __ldg(wp + v), w1 = __ldg(wp + v + 1);
        a0 += e0.x * w0.x + e1.x * w1.x;
        a1 += e0.y * w0.y + e1.y * w1.y;
        a2 += e0.z * w0.z + e1.z * w1.z;
        a3 += e0.w * w0.w + e1.w * w1.w;
    }
    float dot = (a0 + a1) + (a2 + a3);
    float s = __fadd_rn(__fadd_rn(g_A[row], -2.0f * dot), g_nw[code]);
    unsigned long long pk =
        ((unsigned long long)__float_as_uint(s) << 32) | (unsigned)code;
    atomicMin(&g_rbest[row], pk);
}

// ---------------------------------------------------------------------------
// Kernel: convert e -> fp16, compute ||e_row||^2 (fp64 -> fp32). Warp/row.
// ---------------------------------------------------------------------------
__global__ void vq_prep_e(const float* __restrict__ e, int N) {
    int gw   = (blockIdx.x * blockDim.x + threadIdx.x) >> 5;
    int lane = threadIdx.x & 31;
    if (gw >= N) return;
    const float* src = e + (size_t)gw * D + lane * 8;
    float4 v0 = *(const float4*)(src);
    float4 v1 = *(const float4*)(src + 4);
    float x[8] = {v0.x, v0.y, v0.z, v0.w, v1.x, v1.y, v1.z, v1.w};
    double s = 0.0;
    unsigned h[4];
    #pragma unroll
    for (int i = 0; i < 4; i++) {
        float a = x[2*i], b = x[2*i+1];
        s += (double)a * a + (double)b * b;
        h[i] = (unsigned)__half_as_ushort(__float2half_rn(a))
             | ((unsigned)__half_as_ushort(__float2half_rn(b)) << 16);
    }
    *(uint4*)(g_eh + (size_t)gw * D + lane * 8) = make_uint4(h[0], h[1], h[2], h[3]);
    #pragma unroll
    for (int o = 16; o; o >>= 1) s += __shfl_xor_sync(0xffffffffu, s, o);
    if (lane == 0) g_A[gw] = (float)s;
}

// ---------------------------------------------------------------------------
// Kernel: convert w -> fp16, ||w_k||^2, zero counts/loss/flags. Warp/code.
// ---------------------------------------------------------------------------
__global__ void vq_prep_w(const float* __restrict__ w, int K) {
    int gid  = blockIdx.x * blockDim.x + threadIdx.x;
    int gw   = gid >> 5;
    int lane = threadIdx.x & 31;
    if (gid < K)  g_counts[gid] = 0u;
    if (gid == 0) { g_loss = 0.0; g_flagcnt = 0; }
    if (gw >= K) return;
    const float* src = w + (size_t)gw * D + lane * 8;
    float4 v0 = *(const float4*)(src);
    float4 v1 = *(const float4*)(src + 4);
    float x[8] = {v0.x, v0.y, v0.z, v0.w, v1.x, v1.y, v1.z, v1.w};
    double s = 0.0;
    unsigned h[4];
    #pragma unroll
    for (int i = 0; i < 4; i++) {
        float a = x[2*i], b = x[2*i+1];
        s += (double)a * a + (double)b * b;
        h[i] = (unsigned)__half_as_ushort(__float2half_rn(a))
             | ((unsigned)__half_as_ushort(__float2half_rn(b)) << 16);
    }
    *(uint4*)(g_wh + (size_t)gw * D + lane * 8) = make_uint4(h[0], h[1], h[2], h[3]);
    #pragma unroll
    for (int o = 16; o; o >>= 1) s += __shfl_xor_sync(0xffffffffu, s, o);
    if (lane == 0) g_nw[gw] = (float)s;
}

// ---------------------------------------------------------------------------
// Kernel: single-pass fp16 HMMA GEMM + top-2 argmin + near-tie flagging.
// ---------------------------------------------------------------------------
__device__ __forceinline__ void issue_w_step(__half* wbuf, int ct2, int sub2,
                                             int buf, int t) {
    __half* dst = wbuf + buf * (BM * WSTR);
    int dc = sub2 * DCH;
    #pragma unroll
    for (int i = 0; i < 4; i++) {
        int id = t + i * 256;
        int code = id >> 3;
        int dcol = (id & 7) * 8;
        cpa16(dst + code * WSTR + dcol,
              g_wh + (size_t)(ct2 * BM + code) * D + dc + dcol);
    }
    cpa_commit();
}

__global__ void __launch_bounds__(256, 1)
vq_argmin_mma(int K) {
    extern __shared__ char smraw[];
    __half* e_s  = (__half*)smraw;
    __half* wbuf = e_s + BM * ESTR;
    float* A_s  = (float*)(wbuf + 3 * BM * WSTR);
    float* nw_s = A_s + BM;
    float* rS   = nw_s + KMAX;
    float* rC   = rS + BM * 2;
    int*   rI   = (int*)(rC + BM * 2);

    const int t    = threadIdx.x;
    const int lane = t & 31;
    const int wid  = t >> 5;
    const int wrow = wid >> 1;
    const int wcol = wid & 1;
    const int rowbase = blockIdx.x * BM;
    const int lr = lane >> 2;
    const int lk = (lane & 3) * 2;

    {
        const __half* sh = g_eh + (size_t)rowbase * D;
        #pragma unroll
        for (int i = 0; i < 16; i++) {
            int id = t + i * 256;
            int r = id >> 5, dc = (id & 31) * 8;
            *(uint4*)(e_s + r * ESTR + dc) = *(const uint4*)(sh + r * D + dc);
        }
    }
    if (t < BM) A_s[t] = g_A[rowbase + t];
    #pragma unroll
    for (int i = 0; i < 4; i++) nw_s[t + i * 256] = g_nw[t + i * 256];
    __syncthreads();

    float best[4], sec[4];
    int   bidx[4];
    #pragma unroll
    for (int i = 0; i < 4; i++) { best[i] = FLT_MAX; sec[i] = FLT_MAX; bidx[i] = 0; }

    const int NCT = K / BM;                          // 8
    const int NG  = NCT * 4;                         // 32 steps

    issue_w_step(wbuf, 0, 0, 0, t);
    issue_w_step(wbuf, 0, 1, 1, t);

    int g = 0;
    for (int ct = 0; ct < NCT; ct++) {
        float acc[2][8][4];
        #pragma unroll
        for (int mf = 0; mf < 2; mf++)
            #pragma unroll
            for (int nf = 0; nf < 8; nf++)
                #pragma unroll
                for (int v = 0; v < 4; v++) acc[mf][nf][v] = 0.0f;

        #pragma unroll
        for (int sub = 0; sub < 4; sub++, g++) {
            if (g == NG - 1) cpa_wait0(); else cpa_wait1();
            __syncthreads();
            if (g + 2 < NG) issue_w_step(wbuf, (g + 2) >> 2, (g + 2) & 3,
                                         (g + 2) % 3, t);

            const __half* wS = wbuf + (g % 3) * (BM * WSTR);
            const int dc = sub * DCH;

            #pragma unroll
            for (int ks = 0; ks < 4; ks++) {
                const int k0 = dc + ks * 16 + lk;
                const int kl = ks * 16 + lk;
                unsigned a[2][4];
                #pragma unroll
                for (int mf = 0; mf < 2; mf++) {
                    int r = wrow * 32 + mf * 16 + lr;
                    a[mf][0] = *(const unsigned*)(e_s + r * ESTR + k0);
                    a[mf][1] = *(const unsigned*)(e_s + (r + 8) * ESTR + k0);
                    a[mf][2] = *(const unsigned*)(e_s + r * ESTR + k0 + 8);
                    a[mf][3] = *(const unsigned*)(e_s + (r + 8) * ESTR + k0 + 8);
                }
                #pragma unroll
                for (int nf = 0; nf < 8; nf++) {
                    int c = wcol * 64 + nf * 8 + lr;
                    unsigned b0 = *(const unsigned*)(wS + c * WSTR + kl);
                    unsigned b1 = *(const unsigned*)(wS + c * WSTR + kl + 8);
                    mma_f16(acc[0][nf], a[0], b0, b1);
                    mma_f16(acc[1][nf], a[1], b0, b1);
                }
            }
        }

        // ---- epilogue: score + running top-2 ----
        #pragma unroll
        for (int mf = 0; mf < 2; mf++)
        #pragma unroll
        for (int rh = 0; rh < 2; rh++) {
            const int slot = mf * 2 + rh;
            float A = A_s[wrow * 32 + mf * 16 + rh * 8 + lr];
            #pragma unroll
            for (int nf = 0; nf < 8; nf++)
            #pragma unroll
            for (int ci = 0; ci < 2; ci++) {
                int code = ct * BM + wcol * 64 + nf * 8 + (lane & 3) * 2 + ci;
                float dot = acc[mf][nf][rh * 2 + ci];
                float s = __fadd_rn(__fadd_rn(A, -2.0f * dot), nw_s[code]);
                if (s < best[slot] || (s == best[slot] && code < bidx[slot])) {
                    sec[slot]  = best[slot];
                    best[slot] = s; bidx[slot] = code;
                } else if (s < sec[slot]) {
                    sec[slot] = s;
                }
            }
        }
    }

    // ---- cross-lane top-2 merge ----
    #pragma unroll
    for (int slot = 0; slot < 4; slot++) {
        #pragma unroll
        for (int o = 1; o < 4; o <<= 1) {
            float ob = __shfl_xor_sync(0xffffffffu, best[slot], o);
            float os = __shfl_xor_sync(0xffffffffu, sec[slot], o);
            int   oi = __shfl_xor_sync(0xffffffffu, bidx[slot], o);
            if (ob < best[slot] || (ob == best[slot] && oi < bidx[slot])) {
                sec[slot]  = fminf(best[slot], os);
                best[slot] = ob; bidx[slot] = oi;
            } else {
                sec[slot] = fminf(sec[slot], ob);
            }
        }
    }
    if ((lane & 3) == 0) {
        #pragma unroll
        for (int slot = 0; slot < 4; slot++) {
            int mf = slot >> 1, rh = slot & 1;
            int row = wrow * 32 + mf * 16 + rh * 8 + lr;
            rS[row * 2 + wcol] = best[slot];
            rC[row * 2 + wcol] = sec[slot];
            rI[row * 2 + wcol] = bidx[slot];
        }
    }
    __syncthreads();
    if (t < BM) {
        float b0 = rS[t * 2 + 0], b1 = rS[t * 2 + 1];
        float c0 = rC[t * 2 + 0], c1 = rC[t * 2 + 1];
        int   i0 = rI[t * 2 + 0], i1 = rI[t * 2 + 1];
        float fb, fs; int fi;
        if (b1 < b0 || (b1 == b0 && i1 < i0)) {
            fb = b1; fi = i1; fs = fminf(b0, c1);
        } else {
            fb = b0; fi = i0; fs = fminf(c0, b1);
        }
        g_idx[rowbase + t]   = fi;
        g_bestS[rowbase + t] = fb;
        if (fs - fb < RESCUE_THRESH) {
            g_rbest[rowbase + t] = 0xFFFFFFFFFFFFFFFFull;
            int pos = atomicAdd(&g_flagcnt, 1);
            if (pos < NMAX) g_flaglist[pos] = rowbase + t;
        }
    }
}

// ---------------------------------------------------------------------------
// Kernel: candidate re-score of flagged rows. Same fp16 mma pipeline over
// batches of 128 flagged rows; K split 4 ways across blocks (2 code tiles,
// 8 steps each). Scores are bitwise-identical to the argmin pass. Any score
// within CAND_WINDOW of the row's fp16 best triggers an exact fp32 rescore
// + atomicMin into g_rbest (packed scoreBits|code: min score, tie->min code).
// ---------------------------------------------------------------------------
__global__ void __launch_bounds__(256, 1)
vq_candidate(const float* __restrict__ e, const float* __restrict__ w, int K) {
    extern __shared__ char smraw[];
    __half* e_s  = (__half*)smraw;
    __half* wbuf = e_s + BM * ESTR;
    float* A_s     = (float*)(wbuf + 3 * BM * WSTR);
    float* nw2_s   = A_s + BM;          // 256 entries for this k-slice
    float* bestS_s = nw2_s + 256;
    int*   rows_s  = (int*)(bestS_s + BM);

    const int t    = threadIdx.x;
    const int lane = t & 31;
    const int wid  = t >> 5;
    const int wrow = wid >> 1;
    const int wcol = wid & 1;
    const int lr = lane >> 2;
    const int lk = (lane & 3) * 2;

    const int kslice = blockIdx.x & 3;               // 4 K-slices
    const int nflag  = g_flagcnt;

    // nw for this slice's 256 codes
    nw2_s[t] = g_nw[kslice * 256 + t];

    for (int base = (blockIdx.x >> 2) * BM; base < nflag; base += 64 * BM) {
        __syncthreads();                             // protect prior batch readers
        if (t < BM) {
            int s = base + t;
            int r = (s < nflag) ? g_flaglist[s] : -1;
            rows_s[t]  = r;
            A_s[t]     = (r >= 0) ? g_A[r] : 0.0f;
            bestS_s[t] = (r >= 0) ? g_bestS[r] : -FLT_MAX;
        }
        __syncthreads();

        // stage e (fp16) for the batch rows
        #pragma unroll
        for (int i = 0; i < 16; i++) {
            int id = t + i * 256;
            int r = id >> 5, dc = (id & 31) * 8;
            int rw = rows_s[r];
            if (rw >= 0)
                *(uint4*)(e_s + r * ESTR + dc) =
                    *(const uint4*)(g_eh + (size_t)rw * D + dc);
        }

        const int NG = 8;                            // 2 tiles x 4 subs
        issue_w_step(wbuf, kslice * 2 + 0, 0, 0, t);
        issue_w_step(wbuf, kslice * 2 + 0, 1, 1, t);

        int g = 0;
        for (int cti = 0; cti < 2; cti++) {
            const int ct = kslice * 2 + cti;
            float acc[2][8][4];
            #pragma unroll
            for (int mf = 0; mf < 2; mf++)
                #pragma unroll
                for (int nf = 0; nf < 8; nf++)
                    #pragma unroll
                    for (int v = 0; v < 4; v++) acc[mf][nf][v] = 0.0f;

            #pragma unroll
            for (int sub = 0; sub < 4; sub++, g++) {
                if (g == NG - 1) cpa_wait0(); else cpa_wait1();
                __syncthreads();
                if (g + 2 < NG)
                    issue_w_step(wbuf, kslice * 2 + ((g + 2) >> 2), (g + 2) & 3,
                                 (g + 2) % 3, t);

                const __half* wS = wbuf + (g % 3) * (BM * WSTR);
                const int dc = sub * DCH;

                #pragma unroll
                for (int ks = 0; ks < 4; ks++) {
                    const int k0 = dc + ks * 16 + lk;
                    const int kl = ks * 16 + lk;
                    unsigned a[2][4];
                    #pragma unroll
                    for (int mf = 0; mf < 2; mf++) {
                        int r = wrow * 32 + mf * 16 + lr;
                        a[mf][0] = *(const unsigned*)(e_s + r * ESTR + k0);
                        a[mf][1] = *(const unsigned*)(e_s + (r + 8) * ESTR + k0);
                        a[mf][2] = *(const unsigned*)(e_s + r * ESTR + k0 + 8);
                        a[mf][3] = *(const unsigned*)(e_s + (r + 8) * ESTR + k0 + 8);
                    }
                    #pragma unroll
                    for (int nf = 0; nf < 8; nf++) {
                        int c = wcol * 64 + nf * 8 + lr;
                        unsigned b0 = *(const unsigned*)(wS + c * WSTR + kl);
                        unsigned b1 = *(const unsigned*)(wS + c * WSTR + kl + 8);
                        mma_f16(acc[0][nf], a[0], b0, b1);
                        mma_f16(acc[1][nf], a[1], b0, b1);
                    }
                }
            }

            // ---- epilogue: score; exact-rescore candidates ----
            #pragma unroll
            for (int mf = 0; mf < 2; mf++)
            #pragma unroll
            for (int rh = 0; rh < 2; rh++) {
                const int rloc = wrow * 32 + mf * 16 + rh * 8 + lr;
                const int rw = rows_s[rloc];
                if (rw < 0) continue;
                const float A  = A_s[rloc];
                const float bS = bestS_s[rloc];
                #pragma unroll
                for (int nf = 0; nf < 8; nf++)
                #pragma unroll
                for (int ci = 0; ci < 2; ci++) {
                    int code = ct * BM + wcol * 64 + nf * 8 + (lane & 3) * 2 + ci;
                    float dot = acc[mf][nf][rh * 2 + ci];
                    float s = __fadd_rn(__fadd_rn(A, -2.0f * dot),
                                        nw2_s[code - kslice * 256]);
                    if (s < bS + CAND_WINDOW)
                        exact_rescore(e, w, rw, code);
                }
            }
        }
    }
}

// ---------------------------------------------------------------------------
// Kernel: resolve flagged rows' indices from g_rbest.
// ---------------------------------------------------------------------------
__global__ void vq_resolve() {
    int i = blockIdx.x * blockDim.x + threadIdx.x;
    if (i < g_flagcnt) {
        int row = g_flaglist[i];
        g_idx[row] = (int)(unsigned)(g_rbest[row] & 0xFFFFFFFFull);
    }
}

// ---------------------------------------------------------------------------
// Kernel: gather quantized rows, write indices, accumulate loss + counts.
// ---------------------------------------------------------------------------
__global__ void vq_gather_kernel(const float* __restrict__ e,
                                 const float* __restrict__ w,
                                 float* __restrict__ out,
                                 long long out_size, int N) {
    __shared__ double bsum[8];
    const int wl   = threadIdx.x >> 5;
    const int lane = threadIdx.x & 31;
    const int row  = blockIdx.x * 8 + wl;

    float ss = 0.0f;
    int idx = 0;
    if (row < N) {
        idx = g_idx[row];
        const float4* qp = (const float4*)(w + (size_t)idx * D);
        const float4* ep = (const float4*)(e + (size_t)row * D);
        float4*       op = (float4*)(out + (size_t)row * D);
        #pragma unroll
        for (int c = 0; c < 2; c++) {
            int i = lane + c * 32;
            float4 q  = __ldg(&qp[i]);
            float4 ev = ep[i];
            op[i] = q;
            float dx = q.x - ev.x, dy = q.y - ev.y;
            float dz = q.z - ev.z, dw = q.w - ev.w;
            ss += dx * dx + dy * dy + dz * dz + dw * dw;
        }
    }
    #pragma unroll
    for (int o = 16; o; o >>= 1) ss += __shfl_xor_sync(0xffffffffu, ss, o);
    if (lane == 0) {
        bsum[wl] = (double)ss;
        if (row < N) {
            atomicAdd(&g_counts[idx], 1u);
            long long p = (long long)N * D + row;
            if (p < out_size) out[p] = (float)idx;
        }
    }
    __syncthreads();
    if (threadIdx.x == 0) {
        double s = 0.0;
        #pragma unroll
        for (int i = 0; i < 8; i++) s += bsum[i];
        atomicAdd(&g_loss, s);
    }
}

// ---------------------------------------------------------------------------
// Kernel: finalize scalars.
// ---------------------------------------------------------------------------
__global__ void vq_finalize_kernel(float* __restrict__ out, long long out_size,
                                   int N, int K) {
    __shared__ unsigned red[1024];
    int t = threadIdx.x;
    unsigned m = (t < K) ? g_counts[t] : 0u;
    red[t] = m;
    __syncthreads();
    #pragma unroll
    for (int s = 512; s; s >>= 1) {
        if (t < s) { unsigned o = red[t + s]; if (o > red[t]) red[t] = o; }
        __syncthreads();
    }
    if (t == 0) {
        long long base = (long long)N * D + N;
        if (base < out_size)
            out[base] = (float)(g_loss / ((double)N * (double)D));
        if (base + 1 < out_size)
            out[base + 1] = (float)red[0] / (float)N;
    }
}

// ---------------------------------------------------------------------------
extern "C" void kernel_launch(void* const* d_in, const int* in_sizes, int n_in,
                              void* d_out, int out_size) {
    const float* e = (const float*)d_in[0];
    const float* w = (const float*)d_in[1];
    float* out = (float*)d_out;

    int N = in_sizes[0] / D;
    int K = in_sizes[1] / D;
    if (N > NMAX) N = NMAX;
    if (K > KMAX) K = KMAX;
    long long osz = (long long)out_size;

    cudaFuncSetAttribute(vq_argmin_mma,
                         cudaFuncAttributeMaxDynamicSharedMemorySize, SMEM_BYTES);
    cudaFuncSetAttribute(vq_candidate,
                         cudaFuncAttributeMaxDynamicSharedMemorySize, CAND_SMEM_BYTES);

    vq_prep_e<<<(N * 32 + 255) / 256, 256>>>(e, N);
    vq_prep_w<<<(K * 32 + 255) / 256, 256>>>(w, K);
    vq_argmin_mma<<<N / BM, 256, SMEM_BYTES>>>(K);
    vq_candidate<<<256, 256, CAND_SMEM_BYTES>>>(e, w, K);
    vq_resolve<<<NMAX / 256, 256>>>();
    vq_gather_kernel<<<(N + 7) / 8, 256>>>(e, w, out, osz, N);
    vq_finalize_kernel<<<1, 1024>>>(out, osz, N, K);
}

// round 15
// speedup vs baseline: 1.2728x; 1.2728x over previous
#include <cuda_runtime.h>
#include <cuda_fp16.h>
#include <cstdint>
#include <cfloat>

#define D       256
#define KMAX    1024
#define NMAX    65536
#define BM      128
#define ESTR    264     // fp16 stride for e smem tile
#define WSTR    72      // fp16 stride for w smem chunks
#define DCH     64
#define RESCUE_THRESH 1.5e-4f
#define RROWS   16      // rescue rows per block
#define KSLICES 4       // rescue K-split factor

// -------- device scratch (static; no runtime allocation) --------
__device__ __half       g_eh[(size_t)NMAX * D];
__device__ __half       g_wh[(size_t)KMAX * D];
__device__ float        g_nw[KMAX];
__device__ float        g_A[NMAX];
__device__ unsigned long long g_rbest[NMAX];
__device__ int          g_idx[NMAX];
__device__ unsigned int g_counts[KMAX];
__device__ double       g_loss;
__device__ int          g_flagcnt;
__device__ int          g_flaglist[NMAX];

// smem (argmin): e + 3 w buffers + misc
#define SM_E_B     (BM * ESTR * 2)             // 67584
#define SM_WBUF_B  (3 * BM * WSTR * 2)         // 55296
#define SMEM_BYTES (SM_E_B + SM_WBUF_B + BM * 4 + KMAX * 4 \
                    + BM * 2 * 4 + BM * 2 * 4 + BM * 2 * 4)

// rescue dynamic smem
#define RS_BYTES  ((RROWS * 260 + 32 * 260 + 32) * 4)

// ---------------------------------------------------------------------------
// helpers
// ---------------------------------------------------------------------------
__device__ __forceinline__ void cpa16(void* dst, const void* src) {
    unsigned d = (unsigned)__cvta_generic_to_shared(dst);
    asm volatile("cp.async.cg.shared.global [%0], [%1], 16;\n" :: "r"(d), "l"(src));
}
__device__ __forceinline__ void cpa_commit() {
    asm volatile("cp.async.commit_group;\n");
}
__device__ __forceinline__ void cpa_wait0() {
    asm volatile("cp.async.wait_group 0;\n");
}
__device__ __forceinline__ void cpa_wait1() {
    asm volatile("cp.async.wait_group 1;\n");
}
__device__ __forceinline__ void mma_f16(float* c, const unsigned* a, unsigned b0, unsigned b1) {
    asm volatile(
        "mma.sync.aligned.m16n8k16.row.col.f32.f16.f16.f32 "
        "{%0,%1,%2,%3}, {%4,%5,%6,%7}, {%8,%9}, {%0,%1,%2,%3};\n"
        : "+f"(c[0]), "+f"(c[1]), "+f"(c[2]), "+f"(c[3])
        : "r"(a[0]), "r"(a[1]), "r"(a[2]), "r"(a[3]), "r"(b0), "r"(b1));
}

// ---------------------------------------------------------------------------
// Kernel: convert e -> fp16, compute ||e_row||^2 (fp64 -> fp32). Warp/row.
// ---------------------------------------------------------------------------
__global__ void vq_prep_e(const float* __restrict__ e, int N) {
    int gw   = (blockIdx.x * blockDim.x + threadIdx.x) >> 5;
    int lane = threadIdx.x & 31;
    if (gw >= N) return;
    const float* src = e + (size_t)gw * D + lane * 8;
    float4 v0 = *(const float4*)(src);
    float4 v1 = *(const float4*)(src + 4);
    float x[8] = {v0.x, v0.y, v0.z, v0.w, v1.x, v1.y, v1.z, v1.w};
    double s = 0.0;
    unsigned h[4];
    #pragma unroll
    for (int i = 0; i < 4; i++) {
        float a = x[2*i], b = x[2*i+1];
        s += (double)a * a + (double)b * b;
        h[i] = (unsigned)__half_as_ushort(__float2half_rn(a))
             | ((unsigned)__half_as_ushort(__float2half_rn(b)) << 16);
    }
    *(uint4*)(g_eh + (size_t)gw * D + lane * 8) = make_uint4(h[0], h[1], h[2], h[3]);
    #pragma unroll
    for (int o = 16; o; o >>= 1) s += __shfl_xor_sync(0xffffffffu, s, o);
    if (lane == 0) g_A[gw] = (float)s;
}

// ---------------------------------------------------------------------------
// Kernel: convert w -> fp16, ||w_k||^2, zero counts/loss/flags. Warp/code.
// ---------------------------------------------------------------------------
__global__ void vq_prep_w(const float* __restrict__ w, int K) {
    int gid  = blockIdx.x * blockDim.x + threadIdx.x;
    int gw   = gid >> 5;
    int lane = threadIdx.x & 31;
    if (gid < K)  g_counts[gid] = 0u;
    if (gid == 0) { g_loss = 0.0; g_flagcnt = 0; }
    if (gw >= K) return;
    const float* src = w + (size_t)gw * D + lane * 8;
    float4 v0 = *(const float4*)(src);
    float4 v1 = *(const float4*)(src + 4);
    float x[8] = {v0.x, v0.y, v0.z, v0.w, v1.x, v1.y, v1.z, v1.w};
    double s = 0.0;
    unsigned h[4];
    #pragma unroll
    for (int i = 0; i < 4; i++) {
        float a = x[2*i], b = x[2*i+1];
        s += (double)a * a + (double)b * b;
        h[i] = (unsigned)__half_as_ushort(__float2half_rn(a))
             | ((unsigned)__half_as_ushort(__float2half_rn(b)) << 16);
    }
    *(uint4*)(g_wh + (size_t)gw * D + lane * 8) = make_uint4(h[0], h[1], h[2], h[3]);
    #pragma unroll
    for (int o = 16; o; o >>= 1) s += __shfl_xor_sync(0xffffffffu, s, o);
    if (lane == 0) g_nw[gw] = (float)s;
}

// ---------------------------------------------------------------------------
// Kernel: single-pass fp16 HMMA GEMM + top-2 argmin + near-tie flagging.
// (round-13 structure, unchanged except g_rbest priming on flag)
// ---------------------------------------------------------------------------
__device__ __forceinline__ void issue_w_step(__half* wbuf, int g2, int t) {
    int ct2  = g2 >> 2;
    int sub2 = g2 & 3;
    __half* dst = wbuf + (g2 % 3) * (BM * WSTR);
    int dc = sub2 * DCH;
    #pragma unroll
    for (int i = 0; i < 4; i++) {
        int id = t + i * 256;
        int code = id >> 3;
        int dcol = (id & 7) * 8;
        cpa16(dst + code * WSTR + dcol,
              g_wh + (size_t)(ct2 * BM + code) * D + dc + dcol);
    }
    cpa_commit();
}

__global__ void __launch_bounds__(256, 1)
vq_argmin_mma(int K) {
    extern __shared__ char smraw[];
    __half* e_s  = (__half*)smraw;
    __half* wbuf = e_s + BM * ESTR;
    float* A_s  = (float*)(wbuf + 3 * BM * WSTR);
    float* nw_s = A_s + BM;
    float* rS   = nw_s + KMAX;
    float* rC   = rS + BM * 2;
    int*   rI   = (int*)(rC + BM * 2);

    const int t    = threadIdx.x;
    const int lane = t & 31;
    const int wid  = t >> 5;
    const int wrow = wid >> 1;
    const int wcol = wid & 1;
    const int rowbase = blockIdx.x * BM;
    const int lr = lane >> 2;
    const int lk = (lane & 3) * 2;

    {
        const __half* sh = g_eh + (size_t)rowbase * D;
        #pragma unroll
        for (int i = 0; i < 16; i++) {
            int id = t + i * 256;
            int r = id >> 5, dc = (id & 31) * 8;
            *(uint4*)(e_s + r * ESTR + dc) = *(const uint4*)(sh + r * D + dc);
        }
    }
    if (t < BM) A_s[t] = g_A[rowbase + t];
    #pragma unroll
    for (int i = 0; i < 4; i++) nw_s[t + i * 256] = g_nw[t + i * 256];
    __syncthreads();

    float best[4], sec[4];
    int   bidx[4];
    #pragma unroll
    for (int i = 0; i < 4; i++) { best[i] = FLT_MAX; sec[i] = FLT_MAX; bidx[i] = 0; }

    const int NCT = K / BM;                          // 8
    const int NG  = NCT * 4;                         // 32 steps

    issue_w_step(wbuf, 0, t);
    issue_w_step(wbuf, 1, t);

    int g = 0;
    for (int ct = 0; ct < NCT; ct++) {
        float acc[2][8][4];
        #pragma unroll
        for (int mf = 0; mf < 2; mf++)
            #pragma unroll
            for (int nf = 0; nf < 8; nf++)
                #pragma unroll
                for (int v = 0; v < 4; v++) acc[mf][nf][v] = 0.0f;

        #pragma unroll
        for (int sub = 0; sub < 4; sub++, g++) {
            if (g == NG - 1) cpa_wait0(); else cpa_wait1();
            __syncthreads();
            if (g + 2 < NG) issue_w_step(wbuf, g + 2, t);

            const __half* wS = wbuf + (g % 3) * (BM * WSTR);
            const int dc = sub * DCH;

            #pragma unroll
            for (int ks = 0; ks < 4; ks++) {
                const int k0 = dc + ks * 16 + lk;
                const int kl = ks * 16 + lk;
                unsigned a[2][4];
                #pragma unroll
                for (int mf = 0; mf < 2; mf++) {
                    int r = wrow * 32 + mf * 16 + lr;
                    a[mf][0] = *(const unsigned*)(e_s + r * ESTR + k0);
                    a[mf][1] = *(const unsigned*)(e_s + (r + 8) * ESTR + k0);
                    a[mf][2] = *(const unsigned*)(e_s + r * ESTR + k0 + 8);
                    a[mf][3] = *(const unsigned*)(e_s + (r + 8) * ESTR + k0 + 8);
                }
                #pragma unroll
                for (int nf = 0; nf < 8; nf++) {
                    int c = wcol * 64 + nf * 8 + lr;
                    unsigned b0 = *(const unsigned*)(wS + c * WSTR + kl);
                    unsigned b1 = *(const unsigned*)(wS + c * WSTR + kl + 8);
                    mma_f16(acc[0][nf], a[0], b0, b1);
                    mma_f16(acc[1][nf], a[1], b0, b1);
                }
            }
        }

        // ---- epilogue: score + running top-2 ----
        #pragma unroll
        for (int mf = 0; mf < 2; mf++)
        #pragma unroll
        for (int rh = 0; rh < 2; rh++) {
            const int slot = mf * 2 + rh;
            float A = A_s[wrow * 32 + mf * 16 + rh * 8 + lr];
            #pragma unroll
            for (int nf = 0; nf < 8; nf++)
            #pragma unroll
            for (int ci = 0; ci < 2; ci++) {
                int code = ct * BM + wcol * 64 + nf * 8 + (lane & 3) * 2 + ci;
                float dot = acc[mf][nf][rh * 2 + ci];
                float s = __fadd_rn(__fadd_rn(A, -2.0f * dot), nw_s[code]);
                if (s < best[slot] || (s == best[slot] && code < bidx[slot])) {
                    sec[slot]  = best[slot];
                    best[slot] = s; bidx[slot] = code;
                } else if (s < sec[slot]) {
                    sec[slot] = s;
                }
            }
        }
    }

    // ---- cross-lane top-2 merge ----
    #pragma unroll
    for (int slot = 0; slot < 4; slot++) {
        #pragma unroll
        for (int o = 1; o < 4; o <<= 1) {
            float ob = __shfl_xor_sync(0xffffffffu, best[slot], o);
            float os = __shfl_xor_sync(0xffffffffu, sec[slot], o);
            int   oi = __shfl_xor_sync(0xffffffffu, bidx[slot], o);
            if (ob < best[slot] || (ob == best[slot] && oi < bidx[slot])) {
                sec[slot]  = fminf(best[slot], os);
                best[slot] = ob; bidx[slot] = oi;
            } else {
                sec[slot] = fminf(sec[slot], ob);
            }
        }
    }
    if ((lane & 3) == 0) {
        #pragma unroll
        for (int slot = 0; slot < 4; slot++) {
            int mf = slot >> 1, rh = slot & 1;
            int row = wrow * 32 + mf * 16 + rh * 8 + lr;
            rS[row * 2 + wcol] = best[slot];
            rC[row * 2 + wcol] = sec[slot];
            rI[row * 2 + wcol] = bidx[slot];
        }
    }
    __syncthreads();
    if (t < BM) {
        float b0 = rS[t * 2 + 0], b1 = rS[t * 2 + 1];
        float c0 = rC[t * 2 + 0], c1 = rC[t * 2 + 1];
        int   i0 = rI[t * 2 + 0], i1 = rI[t * 2 + 1];
        float fb, fs; int fi;
        if (b1 < b0 || (b1 == b0 && i1 < i0)) {
            fb = b1; fi = i1; fs = fminf(b0, c1);
        } else {
            fb = b0; fi = i0; fs = fminf(c0, b1);
        }
        g_idx[rowbase + t] = fi;
        if (fs - fb < RESCUE_THRESH) {
            g_rbest[rowbase + t] = 0xFFFFFFFFFFFFFFFFull;
            int pos = atomicAdd(&g_flagcnt, 1);
            if (pos < NMAX) g_flaglist[pos] = rowbase + t;
        }
    }
}

// ---------------------------------------------------------------------------
// Kernel: exact fp32 rescore of flagged rows, v4: K-split.
// Block = 16 rows x one K-slice of 256 codes (8 tiles of 32). Per (row,code)
// the dot is computed with the identical summation order as the round-13
// rescue, so scores are bitwise-identical; slice winners merge via atomicMin
// on packed (scoreBits<<32)|code (scores > 0 -> monotone; tie -> min code,
// i.e. first-index semantics).
// ---------------------------------------------------------------------------
__global__ void __launch_bounds__(256)
vq_rescue(const float* __restrict__ e, const float* __restrict__ w, int K) {
    extern __shared__ float rsm[];
    float* e_s = rsm;                   // [RROWS][260]
    float* w_s = e_s + RROWS * 260;     // [32][260]
    float* nwt = w_s + 32 * 260;        // [32]

    const int t    = threadIdx.x;
    const int wid  = t >> 5;
    const int lane = t & 31;
    const int nflag = g_flagcnt;
    const int kbase = (blockIdx.x & (KSLICES - 1)) * (KMAX / KSLICES);

    for (int base = (blockIdx.x / KSLICES) * RROWS; base < nflag;
         base += (gridDim.x / KSLICES) * RROWS) {
        const int s0 = base + wid * 2, s1 = base + wid * 2 + 1;
        const int row0 = (s0 < nflag) ? g_flaglist[s0] : -1;
        const int row1 = (s1 < nflag) ? g_flaglist[s1] : -1;

        if (row0 >= 0) {
            const float4* src = (const float4*)(e + (size_t)row0 * D);
            *(float4*)&e_s[(wid * 2) * 260 + lane * 8]     = src[lane * 2];
            *(float4*)&e_s[(wid * 2) * 260 + lane * 8 + 4] = src[lane * 2 + 1];
        }
        if (row1 >= 0) {
            const float4* src = (const float4*)(e + (size_t)row1 * D);
            *(float4*)&e_s[(wid * 2 + 1) * 260 + lane * 8]     = src[lane * 2];
            *(float4*)&e_s[(wid * 2 + 1) * 260 + lane * 8 + 4] = src[lane * 2 + 1];
        }
        const float A0 = (row0 >= 0) ? g_A[row0] : 0.0f;
        const float A1 = (row1 >= 0) ? g_A[row1] : 0.0f;
        float best0 = FLT_MAX, best1 = FLT_MAX;
        int   bi0 = 0, bi1 = 0;

        for (int cti = 0; cti < (KMAX / KSLICES); cti += 32) {
            const int ct = kbase + cti;
            __syncthreads();
            #pragma unroll
            for (int i = 0; i < 8; i++) {
                int id = t + i * 256;
                int c  = id >> 6;
                int v  = (id & 63) * 4;
                *(float4*)&w_s[c * 260 + v] =
                    __ldg((const float4*)(w + (size_t)(ct + c) * D + v));
            }
            if (t < 32) nwt[t] = g_nw[ct + t];
            __syncthreads();

            const float* wrow = &w_s[lane * 260];
            float a0 = 0.f, a1 = 0.f, a2 = 0.f, a3 = 0.f;
            float c0 = 0.f, c1 = 0.f, c2 = 0.f, c3 = 0.f;
            #pragma unroll
            for (int v = 0; v < D; v += 8) {
                float4 wv0 = *(const float4*)&wrow[v];
                float4 wv1 = *(const float4*)&wrow[v + 4];
                float4 e00 = *(const float4*)&e_s[(wid * 2) * 260 + v];
                float4 e01 = *(const float4*)&e_s[(wid * 2) * 260 + v + 4];
                a0 += e00.x * wv0.x + e01.x * wv1.x;
                a1 += e00.y * wv0.y + e01.y * wv1.y;
                a2 += e00.z * wv0.z + e01.z * wv1.z;
                a3 += e00.w * wv0.w + e01.w * wv1.w;
                float4 e10 = *(const float4*)&e_s[(wid * 2 + 1) * 260 + v];
                float4 e11 = *(const float4*)&e_s[(wid * 2 + 1) * 260 + v + 4];
                c0 += e10.x * wv0.x + e11.x * wv1.x;
                c1 += e10.y * wv0.y + e11.y * wv1.y;
                c2 += e10.z * wv0.z + e11.z * wv1.z;
                c3 += e10.w * wv0.w + e11.w * wv1.w;
            }
            float nv = nwt[lane];
            int code = ct + lane;
            float dot0 = (a0 + a1) + (a2 + a3);
            float dot1 = (c0 + c1) + (c2 + c3);
            float sc0 = __fadd_rn(__fadd_rn(A0, -2.0f * dot0), nv);
            float sc1 = __fadd_rn(__fadd_rn(A1, -2.0f * dot1), nv);
            if (sc0 < best0) { best0 = sc0; bi0 = code; }   // ascending code/lane
            if (sc1 < best1) { best1 = sc1; bi1 = code; }
        }

        #pragma unroll
        for (int o = 16; o; o >>= 1) {
            float ob = __shfl_xor_sync(0xffffffffu, best0, o);
            int   oi = __shfl_xor_sync(0xffffffffu, bi0, o);
            if (ob < best0 || (ob == best0 && oi < bi0)) { best0 = ob; bi0 = oi; }
            float pb = __shfl_xor_sync(0xffffffffu, best1, o);
            int   pi = __shfl_xor_sync(0xffffffffu, bi1, o);
            if (pb < best1 || (pb == best1 && pi < bi1)) { best1 = pb; bi1 = pi; }
        }
        if (lane == 0) {
            if (row0 >= 0) {
                unsigned long long pk =
                    ((unsigned long long)__float_as_uint(best0) << 32) | (unsigned)bi0;
                atomicMin(&g_rbest[row0], pk);
            }
            if (row1 >= 0) {
                unsigned long long pk =
                    ((unsigned long long)__float_as_uint(best1) << 32) | (unsigned)bi1;
                atomicMin(&g_rbest[row1], pk);
            }
        }
        __syncthreads();
    }
}

// ---------------------------------------------------------------------------
// Kernel: resolve flagged rows' indices from g_rbest.
// ---------------------------------------------------------------------------
__global__ void vq_resolve() {
    int i = blockIdx.x * blockDim.x + threadIdx.x;
    if (i < g_flagcnt && i < NMAX) {
        int row = g_flaglist[i];
        g_idx[row] = (int)(unsigned)(g_rbest[row] & 0xFFFFFFFFull);
    }
}

// ---------------------------------------------------------------------------
// Kernel: gather quantized rows, write indices, accumulate loss + counts.
// ---------------------------------------------------------------------------
__global__ void vq_gather_kernel(const float* __restrict__ e,
                                 const float* __restrict__ w,
                                 float* __restrict__ out,
                                 long long out_size, int N) {
    __shared__ double bsum[8];
    const int wl   = threadIdx.x >> 5;
    const int lane = threadIdx.x & 31;
    const int row  = blockIdx.x * 8 + wl;

    float ss = 0.0f;
    int idx = 0;
    if (row < N) {
        idx = g_idx[row];
        const float4* qp = (const float4*)(w + (size_t)idx * D);
        const float4* ep = (const float4*)(e + (size_t)row * D);
        float4*       op = (float4*)(out + (size_t)row * D);
        #pragma unroll
        for (int c = 0; c < 2; c++) {
            int i = lane + c * 32;
            float4 q  = __ldg(&qp[i]);
            float4 ev = ep[i];
            op[i] = q;
            float dx = q.x - ev.x, dy = q.y - ev.y;
            float dz = q.z - ev.z, dw = q.w - ev.w;
            ss += dx * dx + dy * dy + dz * dz + dw * dw;
        }
    }
    #pragma unroll
    for (int o = 16; o; o >>= 1) ss += __shfl_xor_sync(0xffffffffu, ss, o);
    if (lane == 0) {
        bsum[wl] = (double)ss;
        if (row < N) {
            atomicAdd(&g_counts[idx], 1u);
            long long p = (long long)N * D + row;
            if (p < out_size) out[p] = (float)idx;
        }
    }
    __syncthreads();
    if (threadIdx.x == 0) {
        double s = 0.0;
        #pragma unroll
        for (int i = 0; i < 8; i++) s += bsum[i];
        atomicAdd(&g_loss, s);
    }
}

// ---------------------------------------------------------------------------
// Kernel: finalize scalars.
// ---------------------------------------------------------------------------
__global__ void vq_finalize_kernel(float* __restrict__ out, long long out_size,
                                   int N, int K) {
    __shared__ unsigned red[1024];
    int t = threadIdx.x;
    unsigned m = (t < K) ? g_counts[t] : 0u;
    red[t] = m;
    __syncthreads();
    #pragma unroll
    for (int s = 512; s; s >>= 1) {
        if (t < s) { unsigned o = red[t + s]; if (o > red[t]) red[t] = o; }
        __syncthreads();
    }
    if (t == 0) {
        long long base = (long long)N * D + N;
        if (base < out_size)
            out[base] = (float)(g_loss / ((double)N * (double)D));
        if (base + 1 < out_size)
            out[base + 1] = (float)red[0] / (float)N;
    }
}

// ---------------------------------------------------------------------------
extern "C" void kernel_launch(void* const* d_in, const int* in_sizes, int n_in,
                              void* d_out, int out_size) {
    const float* e = (const float*)d_in[0];
    const float* w = (const float*)d_in[1];
    float* out = (float*)d_out;

    int N = in_sizes[0] / D;
    int K = in_sizes[1] / D;
    if (N > NMAX) N = NMAX;
    if (K > KMAX) K = KMAX;
    long long osz = (long long)out_size;

    cudaFuncSetAttribute(vq_argmin_mma,
                         cudaFuncAttributeMaxDynamicSharedMemorySize, SMEM_BYTES);
    cudaFuncSetAttribute(vq_rescue,
                         cudaFuncAttributeMaxDynamicSharedMemorySize, RS_BYTES);

    vq_prep_e<<<(N * 32 + 255) / 256, 256>>>(e, N);
    vq_prep_w<<<(K * 32 + 255) / 256, 256>>>(w, K);
    vq_argmin_mma<<<N / BM, 256, SMEM_BYTES>>>(K);
    vq_rescue<<<1024, 256, RS_BYTES>>>(e, w, K);
    vq_resolve<<<NMAX / 256, 256>>>();
    vq_gather_kernel<<<(N + 7) / 8, 256>>>(e, w, out, osz, N);
    vq_finalize_kernel<<<1, 1024>>>(out, osz, N, K);
}

// round 16
// speedup vs baseline: 1.2993x; 1.0208x over previous
#include <cuda_runtime.h>
#include <cuda_fp16.h>
#include <cstdint>
#include <cfloat>

#define D       256
#define KMAX    1024
#define NMAX    65536
#define BM      128
#define ESTR    264     // fp16 stride for e smem tile
#define WSTR    136     // fp16 stride for w smem chunks (128 k + pad 8)
#define DCH     128     // k-chunk per pipeline step
#define RESCUE_THRESH 1.5e-4f
#define RROWS   16      // rescue rows per block
#define KSLICES 4       // rescue K-split factor

// -------- device scratch (static; no runtime allocation) --------
__device__ __half       g_eh[(size_t)NMAX * D];
__device__ __half       g_wh[(size_t)KMAX * D];
__device__ float        g_nw[KMAX];
__device__ float        g_A[NMAX];
__device__ unsigned long long g_rbest[NMAX];
__device__ int          g_idx[NMAX];
__device__ unsigned int g_counts[KMAX];
__device__ double       g_loss;
__device__ int          g_flagcnt;
__device__ int          g_flaglist[NMAX];

// smem (argmin): e + 3 w buffers + misc
#define SM_E_B     (BM * ESTR * 2)             // 67584
#define SM_WBUF_B  (3 * BM * WSTR * 2)         // 104448
#define SMEM_BYTES (SM_E_B + SM_WBUF_B + BM * 4 + KMAX * 4 \
                    + BM * 2 * 4 + BM * 2 * 4 + BM * 2 * 4)   // ~179.7 KB

// rescue dynamic smem
#define RS_BYTES  ((RROWS * 260 + 32 * 260 + 32) * 4)

// ---------------------------------------------------------------------------
// helpers
// ---------------------------------------------------------------------------
__device__ __forceinline__ void cpa16(void* dst, const void* src) {
    unsigned d = (unsigned)__cvta_generic_to_shared(dst);
    asm volatile("cp.async.cg.shared.global [%0], [%1], 16;\n" :: "r"(d), "l"(src));
}
__device__ __forceinline__ void cpa_commit() {
    asm volatile("cp.async.commit_group;\n");
}
__device__ __forceinline__ void cpa_wait0() {
    asm volatile("cp.async.wait_group 0;\n");
}
__device__ __forceinline__ void cpa_wait1() {
    asm volatile("cp.async.wait_group 1;\n");
}
__device__ __forceinline__ void mma_f16(float* c, const unsigned* a, unsigned b0, unsigned b1) {
    asm volatile(
        "mma.sync.aligned.m16n8k16.row.col.f32.f16.f16.f32 "
        "{%0,%1,%2,%3}, {%4,%5,%6,%7}, {%8,%9}, {%0,%1,%2,%3};\n"
        : "+f"(c[0]), "+f"(c[1]), "+f"(c[2]), "+f"(c[3])
        : "r"(a[0]), "r"(a[1]), "r"(a[2]), "r"(a[3]), "r"(b0), "r"(b1));
}

// ---------------------------------------------------------------------------
// Kernel: convert e -> fp16, compute ||e_row||^2 (fp64 -> fp32). Warp/row.
// ---------------------------------------------------------------------------
__global__ void vq_prep_e(const float* __restrict__ e, int N) {
    int gw   = (blockIdx.x * blockDim.x + threadIdx.x) >> 5;
    int lane = threadIdx.x & 31;
    if (gw >= N) return;
    const float* src = e + (size_t)gw * D + lane * 8;
    float4 v0 = *(const float4*)(src);
    float4 v1 = *(const float4*)(src + 4);
    float x[8] = {v0.x, v0.y, v0.z, v0.w, v1.x, v1.y, v1.z, v1.w};
    double s = 0.0;
    unsigned h[4];
    #pragma unroll
    for (int i = 0; i < 4; i++) {
        float a = x[2*i], b = x[2*i+1];
        s += (double)a * a + (double)b * b;
        h[i] = (unsigned)__half_as_ushort(__float2half_rn(a))
             | ((unsigned)__half_as_ushort(__float2half_rn(b)) << 16);
    }
    *(uint4*)(g_eh + (size_t)gw * D + lane * 8) = make_uint4(h[0], h[1], h[2], h[3]);
    #pragma unroll
    for (int o = 16; o; o >>= 1) s += __shfl_xor_sync(0xffffffffu, s, o);
    if (lane == 0) g_A[gw] = (float)s;
}

// ---------------------------------------------------------------------------
// Kernel: convert w -> fp16, ||w_k||^2, zero counts/loss/flags. Warp/code.
// ---------------------------------------------------------------------------
__global__ void vq_prep_w(const float* __restrict__ w, int K) {
    int gid  = blockIdx.x * blockDim.x + threadIdx.x;
    int gw   = gid >> 5;
    int lane = threadIdx.x & 31;
    if (gid < K)  g_counts[gid] = 0u;
    if (gid == 0) { g_loss = 0.0; g_flagcnt = 0; }
    if (gw >= K) return;
    const float* src = w + (size_t)gw * D + lane * 8;
    float4 v0 = *(const float4*)(src);
    float4 v1 = *(const float4*)(src + 4);
    float x[8] = {v0.x, v0.y, v0.z, v0.w, v1.x, v1.y, v1.z, v1.w};
    double s = 0.0;
    unsigned h[4];
    #pragma unroll
    for (int i = 0; i < 4; i++) {
        float a = x[2*i], b = x[2*i+1];
        s += (double)a * a + (double)b * b;
        h[i] = (unsigned)__half_as_ushort(__float2half_rn(a))
             | ((unsigned)__half_as_ushort(__float2half_rn(b)) << 16);
    }
    *(uint4*)(g_wh + (size_t)gw * D + lane * 8) = make_uint4(h[0], h[1], h[2], h[3]);
    #pragma unroll
    for (int o = 16; o; o >>= 1) s += __shfl_xor_sync(0xffffffffu, s, o);
    if (lane == 0) g_nw[gw] = (float)s;
}

// ---------------------------------------------------------------------------
// Kernel: single-pass fp16 HMMA GEMM + top-2 argmin + near-tie flagging.
// 16 steps (8 code tiles x 2 k-chunks of 128); 3-buffer cp.async pipeline,
// depth 2. Same k-order and mma sequence as round 13 -> scores bitwise equal.
// ---------------------------------------------------------------------------
__device__ __forceinline__ void issue_w_step(__half* wbuf, int g2, int t) {
    int ct2  = g2 >> 1;                 // code tile
    int sub2 = g2 & 1;                  // k half
    __half* dst = wbuf + (g2 % 3) * (BM * WSTR);
    int dc = sub2 * DCH;
    #pragma unroll
    for (int i = 0; i < 8; i++) {       // 2048 chunks of 8 halves
        int id = t + i * 256;
        int code = id >> 4;
        int dcol = (id & 15) * 8;
        cpa16(dst + code * WSTR + dcol,
              g_wh + (size_t)(ct2 * BM + code) * D + dc + dcol);
    }
    cpa_commit();
}

__global__ void __launch_bounds__(256, 1)
vq_argmin_mma(int K) {
    extern __shared__ char smraw[];
    __half* e_s  = (__half*)smraw;
    __half* wbuf = e_s + BM * ESTR;
    float* A_s  = (float*)(wbuf + 3 * BM * WSTR);
    float* nw_s = A_s + BM;
    float* rS   = nw_s + KMAX;
    float* rC   = rS + BM * 2;
    int*   rI   = (int*)(rC + BM * 2);

    const int t    = threadIdx.x;
    const int lane = t & 31;
    const int wid  = t >> 5;
    const int wrow = wid >> 1;
    const int wcol = wid & 1;
    const int rowbase = blockIdx.x * BM;
    const int lr = lane >> 2;
    const int lk = (lane & 3) * 2;

    {
        const __half* sh = g_eh + (size_t)rowbase * D;
        #pragma unroll
        for (int i = 0; i < 16; i++) {
            int id = t + i * 256;
            int r = id >> 5, dc = (id & 31) * 8;
            *(uint4*)(e_s + r * ESTR + dc) = *(const uint4*)(sh + r * D + dc);
        }
    }
    if (t < BM) A_s[t] = g_A[rowbase + t];
    #pragma unroll
    for (int i = 0; i < 4; i++) nw_s[t + i * 256] = g_nw[t + i * 256];
    __syncthreads();

    float best[4], sec[4];
    int   bidx[4];
    #pragma unroll
    for (int i = 0; i < 4; i++) { best[i] = FLT_MAX; sec[i] = FLT_MAX; bidx[i] = 0; }

    const int NCT = K / BM;                          // 8
    const int NG  = NCT * 2;                         // 16 steps

    issue_w_step(wbuf, 0, t);
    issue_w_step(wbuf, 1, t);

    int g = 0;
    for (int ct = 0; ct < NCT; ct++) {
        float acc[2][8][4];
        #pragma unroll
        for (int mf = 0; mf < 2; mf++)
            #pragma unroll
            for (int nf = 0; nf < 8; nf++)
                #pragma unroll
                for (int v = 0; v < 4; v++) acc[mf][nf][v] = 0.0f;

        #pragma unroll
        for (int sub = 0; sub < 2; sub++, g++) {
            if (g == NG - 1) cpa_wait0(); else cpa_wait1();
            __syncthreads();
            if (g + 2 < NG) issue_w_step(wbuf, g + 2, t);

            const __half* wS = wbuf + (g % 3) * (BM * WSTR);
            const int dc = sub * DCH;

            #pragma unroll
            for (int ks = 0; ks < 8; ks++) {
                const int k0 = dc + ks * 16 + lk;    // e smem offset
                const int kl = ks * 16 + lk;         // w smem offset
                unsigned a[2][4];
                #pragma unroll
                for (int mf = 0; mf < 2; mf++) {
                    int r = wrow * 32 + mf * 16 + lr;
                    a[mf][0] = *(const unsigned*)(e_s + r * ESTR + k0);
                    a[mf][1] = *(const unsigned*)(e_s + (r + 8) * ESTR + k0);
                    a[mf][2] = *(const unsigned*)(e_s + r * ESTR + k0 + 8);
                    a[mf][3] = *(const unsigned*)(e_s + (r + 8) * ESTR + k0 + 8);
                }
                #pragma unroll
                for (int nf = 0; nf < 8; nf++) {
                    int c = wcol * 64 + nf * 8 + lr;
                    unsigned b0 = *(const unsigned*)(wS + c * WSTR + kl);
                    unsigned b1 = *(const unsigned*)(wS + c * WSTR + kl + 8);
                    mma_f16(acc[0][nf], a[0], b0, b1);
                    mma_f16(acc[1][nf], a[1], b0, b1);
                }
            }
        }

        // ---- epilogue: score + running top-2 ----
        #pragma unroll
        for (int mf = 0; mf < 2; mf++)
        #pragma unroll
        for (int rh = 0; rh < 2; rh++) {
            const int slot = mf * 2 + rh;
            float A = A_s[wrow * 32 + mf * 16 + rh * 8 + lr];
            #pragma unroll
            for (int nf = 0; nf < 8; nf++)
            #pragma unroll
            for (int ci = 0; ci < 2; ci++) {
                int code = ct * BM + wcol * 64 + nf * 8 + (lane & 3) * 2 + ci;
                float dot = acc[mf][nf][rh * 2 + ci];
                float s = __fadd_rn(__fadd_rn(A, -2.0f * dot), nw_s[code]);
                if (s < best[slot] || (s == best[slot] && code < bidx[slot])) {
                    sec[slot]  = best[slot];
                    best[slot] = s; bidx[slot] = code;
                } else if (s < sec[slot]) {
                    sec[slot] = s;
                }
            }
        }
    }

    // ---- cross-lane top-2 merge ----
    #pragma unroll
    for (int slot = 0; slot < 4; slot++) {
        #pragma unroll
        for (int o = 1; o < 4; o <<= 1) {
            float ob = __shfl_xor_sync(0xffffffffu, best[slot], o);
            float os = __shfl_xor_sync(0xffffffffu, sec[slot], o);
            int   oi = __shfl_xor_sync(0xffffffffu, bidx[slot], o);
            if (ob < best[slot] || (ob == best[slot] && oi < bidx[slot])) {
                sec[slot]  = fminf(best[slot], os);
                best[slot] = ob; bidx[slot] = oi;
            } else {
                sec[slot] = fminf(sec[slot], ob);
            }
        }
    }
    if ((lane & 3) == 0) {
        #pragma unroll
        for (int slot = 0; slot < 4; slot++) {
            int mf = slot >> 1, rh = slot & 1;
            int row = wrow * 32 + mf * 16 + rh * 8 + lr;
            rS[row * 2 + wcol] = best[slot];
            rC[row * 2 + wcol] = sec[slot];
            rI[row * 2 + wcol] = bidx[slot];
        }
    }
    __syncthreads();
    if (t < BM) {
        float b0 = rS[t * 2 + 0], b1 = rS[t * 2 + 1];
        float c0 = rC[t * 2 + 0], c1 = rC[t * 2 + 1];
        int   i0 = rI[t * 2 + 0], i1 = rI[t * 2 + 1];
        float fb, fs; int fi;
        if (b1 < b0 || (b1 == b0 && i1 < i0)) {
            fb = b1; fi = i1; fs = fminf(b0, c1);
        } else {
            fb = b0; fi = i0; fs = fminf(c0, b1);
        }
        g_idx[rowbase + t] = fi;
        if (fs - fb < RESCUE_THRESH) {
            g_rbest[rowbase + t] = 0xFFFFFFFFFFFFFFFFull;
            int pos = atomicAdd(&g_flagcnt, 1);
            if (pos < NMAX) g_flaglist[pos] = rowbase + t;
        }
    }
}

// ---------------------------------------------------------------------------
// Kernel: exact fp32 rescore of flagged rows, v4: K-split (unchanged).
// ---------------------------------------------------------------------------
__global__ void __launch_bounds__(256)
vq_rescue(const float* __restrict__ e, const float* __restrict__ w, int K) {
    extern __shared__ float rsm[];
    float* e_s = rsm;                   // [RROWS][260]
    float* w_s = e_s + RROWS * 260;     // [32][260]
    float* nwt = w_s + 32 * 260;        // [32]

    const int t    = threadIdx.x;
    const int wid  = t >> 5;
    const int lane = t & 31;
    const int nflag = g_flagcnt;
    const int kbase = (blockIdx.x & (KSLICES - 1)) * (KMAX / KSLICES);

    for (int base = (blockIdx.x / KSLICES) * RROWS; base < nflag;
         base += (gridDim.x / KSLICES) * RROWS) {
        const int s0 = base + wid * 2, s1 = base + wid * 2 + 1;
        const int row0 = (s0 < nflag) ? g_flaglist[s0] : -1;
        const int row1 = (s1 < nflag) ? g_flaglist[s1] : -1;

        if (row0 >= 0) {
            const float4* src = (const float4*)(e + (size_t)row0 * D);
            *(float4*)&e_s[(wid * 2) * 260 + lane * 8]     = src[lane * 2];
            *(float4*)&e_s[(wid * 2) * 260 + lane * 8 + 4] = src[lane * 2 + 1];
        }
        if (row1 >= 0) {
            const float4* src = (const float4*)(e + (size_t)row1 * D);
            *(float4*)&e_s[(wid * 2 + 1) * 260 + lane * 8]     = src[lane * 2];
            *(float4*)&e_s[(wid * 2 + 1) * 260 + lane * 8 + 4] = src[lane * 2 + 1];
        }
        const float A0 = (row0 >= 0) ? g_A[row0] : 0.0f;
        const float A1 = (row1 >= 0) ? g_A[row1] : 0.0f;
        float best0 = FLT_MAX, best1 = FLT_MAX;
        int   bi0 = 0, bi1 = 0;

        for (int cti = 0; cti < (KMAX / KSLICES); cti += 32) {
            const int ct = kbase + cti;
            __syncthreads();
            #pragma unroll
            for (int i = 0; i < 8; i++) {
                int id = t + i * 256;
                int c  = id >> 6;
                int v  = (id & 63) * 4;
                *(float4*)&w_s[c * 260 + v] =
                    __ldg((const float4*)(w + (size_t)(ct + c) * D + v));
            }
            if (t < 32) nwt[t] = g_nw[ct + t];
            __syncthreads();

            const float* wrow = &w_s[lane * 260];
            float a0 = 0.f, a1 = 0.f, a2 = 0.f, a3 = 0.f;
            float c0 = 0.f, c1 = 0.f, c2 = 0.f, c3 = 0.f;
            #pragma unroll
            for (int v = 0; v < D; v += 8) {
                float4 wv0 = *(const float4*)&wrow[v];
                float4 wv1 = *(const float4*)&wrow[v + 4];
                float4 e00 = *(const float4*)&e_s[(wid * 2) * 260 + v];
                float4 e01 = *(const float4*)&e_s[(wid * 2) * 260 + v + 4];
                a0 += e00.x * wv0.x + e01.x * wv1.x;
                a1 += e00.y * wv0.y + e01.y * wv1.y;
                a2 += e00.z * wv0.z + e01.z * wv1.z;
                a3 += e00.w * wv0.w + e01.w * wv1.w;
                float4 e10 = *(const float4*)&e_s[(wid * 2 + 1) * 260 + v];
                float4 e11 = *(const float4*)&e_s[(wid * 2 + 1) * 260 + v + 4];
                c0 += e10.x * wv0.x + e11.x * wv1.x;
                c1 += e10.y * wv0.y + e11.y * wv1.y;
                c2 += e10.z * wv0.z + e11.z * wv1.z;
                c3 += e10.w * wv0.w + e11.w * wv1.w;
            }
            float nv = nwt[lane];
            int code = ct + lane;
            float dot0 = (a0 + a1) + (a2 + a3);
            float dot1 = (c0 + c1) + (c2 + c3);
            float sc0 = __fadd_rn(__fadd_rn(A0, -2.0f * dot0), nv);
            float sc1 = __fadd_rn(__fadd_rn(A1, -2.0f * dot1), nv);
            if (sc0 < best0) { best0 = sc0; bi0 = code; }
            if (sc1 < best1) { best1 = sc1; bi1 = code; }
        }

        #pragma unroll
        for (int o = 16; o; o >>= 1) {
            float ob = __shfl_xor_sync(0xffffffffu, best0, o);
            int   oi = __shfl_xor_sync(0xffffffffu, bi0, o);
            if (ob < best0 || (ob == best0 && oi < bi0)) { best0 = ob; bi0 = oi; }
            float pb = __shfl_xor_sync(0xffffffffu, best1, o);
            int   pi = __shfl_xor_sync(0xffffffffu, bi1, o);
            if (pb < best1 || (pb == best1 && pi < bi1)) { best1 = pb; bi1 = pi; }
        }
        if (lane == 0) {
            if (row0 >= 0) {
                unsigned long long pk =
                    ((unsigned long long)__float_as_uint(best0) << 32) | (unsigned)bi0;
                atomicMin(&g_rbest[row0], pk);
            }
            if (row1 >= 0) {
                unsigned long long pk =
                    ((unsigned long long)__float_as_uint(best1) << 32) | (unsigned)bi1;
                atomicMin(&g_rbest[row1], pk);
            }
        }
        __syncthreads();
    }
}

// ---------------------------------------------------------------------------
// Kernel: resolve flagged rows' indices from g_rbest.
// ---------------------------------------------------------------------------
__global__ void vq_resolve() {
    int i = blockIdx.x * blockDim.x + threadIdx.x;
    if (i < g_flagcnt && i < NMAX) {
        int row = g_flaglist[i];
        g_idx[row] = (int)(unsigned)(g_rbest[row] & 0xFFFFFFFFull);
    }
}

// ---------------------------------------------------------------------------
// Kernel: gather quantized rows, write indices, accumulate loss + counts.
// ---------------------------------------------------------------------------
__global__ void vq_gather_kernel(const float* __restrict__ e,
                                 const float* __restrict__ w,
                                 float* __restrict__ out,
                                 long long out_size, int N) {
    __shared__ double bsum[8];
    const int wl   = threadIdx.x >> 5;
    const int lane = threadIdx.x & 31;
    const int row  = blockIdx.x * 8 + wl;

    float ss = 0.0f;
    int idx = 0;
    if (row < N) {
        idx = g_idx[row];
        const float4* qp = (const float4*)(w + (size_t)idx * D);
        const float4* ep = (const float4*)(e + (size_t)row * D);
        float4*       op = (float4*)(out + (size_t)row * D);
        #pragma unroll
        for (int c = 0; c < 2; c++) {
            int i = lane + c * 32;
            float4 q  = __ldg(&qp[i]);
            float4 ev = ep[i];
            op[i] = q;
            float dx = q.x - ev.x, dy = q.y - ev.y;
            float dz = q.z - ev.z, dw = q.w - ev.w;
            ss += dx * dx + dy * dy + dz * dz + dw * dw;
        }
    }
    #pragma unroll
    for (int o = 16; o; o >>= 1) ss += __shfl_xor_sync(0xffffffffu, ss, o);
    if (lane == 0) {
        bsum[wl] = (double)ss;
        if (row < N) {
            atomicAdd(&g_counts[idx], 1u);
            long long p = (long long)N * D + row;
            if (p < out_size) out[p] = (float)idx;
        }
    }
    __syncthreads();
    if (threadIdx.x == 0) {
        double s = 0.0;
        #pragma unroll
        for (int i = 0; i < 8; i++) s += bsum[i];
        atomicAdd(&g_loss, s);
    }
}

// ---------------------------------------------------------------------------
// Kernel: finalize scalars.
// ---------------------------------------------------------------------------
__global__ void vq_finalize_kernel(float* __restrict__ out, long long out_size,
                                   int N, int K) {
    __shared__ unsigned red[1024];
    int t = threadIdx.x;
    unsigned m = (t < K) ? g_counts[t] : 0u;
    red[t] = m;
    __syncthreads();
    #pragma unroll
    for (int s = 512; s; s >>= 1) {
        if (t < s) { unsigned o = red[t + s]; if (o > red[t]) red[t] = o; }
        __syncthreads();
    }
    if (t == 0) {
        long long base = (long long)N * D + N;
        if (base < out_size)
            out[base] = (float)(g_loss / ((double)N * (double)D));
        if (base + 1 < out_size)
            out[base + 1] = (float)red[0] / (float)N;
    }
}

// ---------------------------------------------------------------------------
extern "C" void kernel_launch(void* const* d_in, const int* in_sizes, int n_in,
                              void* d_out, int out_size) {
    const float* e = (const float*)d_in[0];
    const float* w = (const float*)d_in[1];
    float* out = (float*)d_out;

    int N = in_sizes[0] / D;
    int K = in_sizes[1] / D;
    if (N > NMAX) N = NMAX;
    if (K > KMAX) K = KMAX;
    long long osz = (long long)out_size;

    cudaFuncSetAttribute(vq_argmin_mma,
                         cudaFuncAttributeMaxDynamicSharedMemorySize, SMEM_BYTES);
    cudaFuncSetAttribute(vq_rescue,
                         cudaFuncAttributeMaxDynamicSharedMemorySize, RS_BYTES);

    vq_prep_e<<<(N * 32 + 255) / 256, 256>>>(e, N);
    vq_prep_w<<<(K * 32 + 255) / 256, 256>>>(w, K);
    vq_argmin_mma<<<N / BM, 256, SMEM_BYTES>>>(K);
    vq_rescue<<<1024, 256, RS_BYTES>>>(e, w, K);
    vq_resolve<<<NMAX / 256, 256>>>();
    vq_gather_kernel<<<(N + 7) / 8, 256>>>(e, w, out, osz, N);
    vq_finalize_kernel<<<1, 1024>>>(out, osz, N, K);
}

// round 17
// speedup vs baseline: 1.3682x; 1.0530x over previous
#include <cuda_runtime.h>
#include <cuda_fp16.h>
#include <cstdint>
#include <cfloat>

#define D       256
#define KMAX    1024
#define NMAX    65536
#define BM      128
#define ESTR    264     // fp16 stride for e smem tile
#define WSTR    136     // fp16 stride for w smem chunks (128 k + pad 8)
#define DCH     128     // k-chunk per pipeline step
#define NTHR    512     // 16 warps
#define RESCUE_THRESH 1.5e-4f
#define RROWS   16      // rescue rows per block
#define KSLICES 4       // rescue K-split factor

// -------- device scratch (static; no runtime allocation) --------
__device__ __half       g_eh[(size_t)NMAX * D];
__device__ __half       g_wh[(size_t)KMAX * D];
__device__ float        g_nw[KMAX];
__device__ float        g_A[NMAX];
__device__ unsigned long long g_rbest[NMAX];
__device__ int          g_idx[NMAX];
__device__ unsigned int g_counts[KMAX];
__device__ double       g_loss;
__device__ int          g_flagcnt;
__device__ int          g_flaglist[NMAX];

// smem (argmin): e + 3 w buffers + misc (reduce arrays now BM*4 wide)
#define SM_E_B     (BM * ESTR * 2)             // 67584
#define SM_WBUF_B  (3 * BM * WSTR * 2)         // 104448
#define SMEM_BYTES (SM_E_B + SM_WBUF_B + BM * 4 + KMAX * 4 \
                    + BM * 4 * 4 + BM * 4 * 4 + BM * 4 * 4)   // ~182.6 KB

// rescue dynamic smem
#define RS_BYTES  ((RROWS * 260 + 32 * 260 + 32) * 4)

// ---------------------------------------------------------------------------
// helpers
// ---------------------------------------------------------------------------
__device__ __forceinline__ void cpa16(void* dst, const void* src) {
    unsigned d = (unsigned)__cvta_generic_to_shared(dst);
    asm volatile("cp.async.cg.shared.global [%0], [%1], 16;\n" :: "r"(d), "l"(src));
}
__device__ __forceinline__ void cpa_commit() {
    asm volatile("cp.async.commit_group;\n");
}
__device__ __forceinline__ void cpa_wait0() {
    asm volatile("cp.async.wait_group 0;\n");
}
__device__ __forceinline__ void cpa_wait1() {
    asm volatile("cp.async.wait_group 1;\n");
}
__device__ __forceinline__ void mma_f16(float* c, const unsigned* a, unsigned b0, unsigned b1) {
    asm volatile(
        "mma.sync.aligned.m16n8k16.row.col.f32.f16.f16.f32 "
        "{%0,%1,%2,%3}, {%4,%5,%6,%7}, {%8,%9}, {%0,%1,%2,%3};\n"
        : "+f"(c[0]), "+f"(c[1]), "+f"(c[2]), "+f"(c[3])
        : "r"(a[0]), "r"(a[1]), "r"(a[2]), "r"(a[3]), "r"(b0), "r"(b1));
}

// ---------------------------------------------------------------------------
// Kernel: convert e -> fp16, compute ||e_row||^2 (fp64 -> fp32). Warp/row.
// ---------------------------------------------------------------------------
__global__ void vq_prep_e(const float* __restrict__ e, int N) {
    int gw   = (blockIdx.x * blockDim.x + threadIdx.x) >> 5;
    int lane = threadIdx.x & 31;
    if (gw >= N) return;
    const float* src = e + (size_t)gw * D + lane * 8;
    float4 v0 = *(const float4*)(src);
    float4 v1 = *(const float4*)(src + 4);
    float x[8] = {v0.x, v0.y, v0.z, v0.w, v1.x, v1.y, v1.z, v1.w};
    double s = 0.0;
    unsigned h[4];
    #pragma unroll
    for (int i = 0; i < 4; i++) {
        float a = x[2*i], b = x[2*i+1];
        s += (double)a * a + (double)b * b;
        h[i] = (unsigned)__half_as_ushort(__float2half_rn(a))
             | ((unsigned)__half_as_ushort(__float2half_rn(b)) << 16);
    }
    *(uint4*)(g_eh + (size_t)gw * D + lane * 8) = make_uint4(h[0], h[1], h[2], h[3]);
    #pragma unroll
    for (int o = 16; o; o >>= 1) s += __shfl_xor_sync(0xffffffffu, s, o);
    if (lane == 0) g_A[gw] = (float)s;
}

// ---------------------------------------------------------------------------
// Kernel: convert w -> fp16, ||w_k||^2, zero counts/loss/flags. Warp/code.
// ---------------------------------------------------------------------------
__global__ void vq_prep_w(const float* __restrict__ w, int K) {
    int gid  = blockIdx.x * blockDim.x + threadIdx.x;
    int gw   = gid >> 5;
    int lane = threadIdx.x & 31;
    if (gid < K)  g_counts[gid] = 0u;
    if (gid == 0) { g_loss = 0.0; g_flagcnt = 0; }
    if (gw >= K) return;
    const float* src = w + (size_t)gw * D + lane * 8;
    float4 v0 = *(const float4*)(src);
    float4 v1 = *(const float4*)(src + 4);
    float x[8] = {v0.x, v0.y, v0.z, v0.w, v1.x, v1.y, v1.z, v1.w};
    double s = 0.0;
    unsigned h[4];
    #pragma unroll
    for (int i = 0; i < 4; i++) {
        float a = x[2*i], b = x[2*i+1];
        s += (double)a * a + (double)b * b;
        h[i] = (unsigned)__half_as_ushort(__float2half_rn(a))
             | ((unsigned)__half_as_ushort(__float2half_rn(b)) << 16);
    }
    *(uint4*)(g_wh + (size_t)gw * D + lane * 8) = make_uint4(h[0], h[1], h[2], h[3]);
    #pragma unroll
    for (int o = 16; o; o >>= 1) s += __shfl_xor_sync(0xffffffffu, s, o);
    if (lane == 0) g_nw[gw] = (float)s;
}

// ---------------------------------------------------------------------------
// Kernel: single-pass fp16 HMMA GEMM + top-2 argmin + near-tie flagging.
// 512 threads: warp = (wrow 0-3) x (wcol 0-3); each warp 32 rows x 32 codes.
// 16 steps (8 code tiles x 2 k-chunks of 128); 3-buffer cp.async, depth 2.
// Per-(row,code) accumulation chain identical to round 16 -> scores bitwise
// equal; 4-way per-row merge preserves first-index tie-break (wcol order ==
// ascending code order).
// ---------------------------------------------------------------------------
__device__ __forceinline__ void issue_w_step(__half* wbuf, int g2, int t) {
    int ct2  = g2 >> 1;                 // code tile
    int sub2 = g2 & 1;                  // k half
    __half* dst = wbuf + (g2 % 3) * (BM * WSTR);
    int dc = sub2 * DCH;
    #pragma unroll
    for (int i = 0; i < 4; i++) {       // 2048 chunks of 8 halves / 512 thr
        int id = t + i * NTHR;
        int code = id >> 4;
        int dcol = (id & 15) * 8;
        cpa16(dst + code * WSTR + dcol,
              g_wh + (size_t)(ct2 * BM + code) * D + dc + dcol);
    }
    cpa_commit();
}

__global__ void __launch_bounds__(NTHR, 1)
vq_argmin_mma(int K) {
    extern __shared__ char smraw[];
    __half* e_s  = (__half*)smraw;
    __half* wbuf = e_s + BM * ESTR;
    float* A_s  = (float*)(wbuf + 3 * BM * WSTR);
    float* nw_s = A_s + BM;
    float* rS   = nw_s + KMAX;          // [BM][4]
    float* rC   = rS + BM * 4;
    int*   rI   = (int*)(rC + BM * 4);

    const int t    = threadIdx.x;
    const int lane = t & 31;
    const int wid  = t >> 5;            // 0..15
    const int wrow = wid >> 2;          // 0..3 (32 rows each)
    const int wcol = wid & 3;           // 0..3 (32 codes each)
    const int rowbase = blockIdx.x * BM;
    const int lr = lane >> 2;
    const int lk = (lane & 3) * 2;

    {
        const __half* sh = g_eh + (size_t)rowbase * D;
        #pragma unroll
        for (int i = 0; i < 8; i++) {   // 4096 chunks / 512 thr
            int id = t + i * NTHR;
            int r = id >> 5, dc = (id & 31) * 8;
            *(uint4*)(e_s + r * ESTR + dc) = *(const uint4*)(sh + r * D + dc);
        }
    }
    if (t < BM) A_s[t] = g_A[rowbase + t];
    #pragma unroll
    for (int i = 0; i < 2; i++) nw_s[t + i * NTHR] = g_nw[t + i * NTHR];
    __syncthreads();

    float best[4], sec[4];
    int   bidx[4];
    #pragma unroll
    for (int i = 0; i < 4; i++) { best[i] = FLT_MAX; sec[i] = FLT_MAX; bidx[i] = 0; }

    const int NCT = K / BM;                          // 8
    const int NG  = NCT * 2;                         // 16 steps

    issue_w_step(wbuf, 0, t);
    issue_w_step(wbuf, 1, t);

    int g = 0;
    for (int ct = 0; ct < NCT; ct++) {
        float acc[2][4][4];
        #pragma unroll
        for (int mf = 0; mf < 2; mf++)
            #pragma unroll
            for (int nf = 0; nf < 4; nf++)
                #pragma unroll
                for (int v = 0; v < 4; v++) acc[mf][nf][v] = 0.0f;

        #pragma unroll
        for (int sub = 0; sub < 2; sub++, g++) {
            if (g == NG - 1) cpa_wait0(); else cpa_wait1();
            __syncthreads();
            if (g + 2 < NG) issue_w_step(wbuf, g + 2, t);

            const __half* wS = wbuf + (g % 3) * (BM * WSTR);
            const int dc = sub * DCH;

            #pragma unroll
            for (int ks = 0; ks < 8; ks++) {
                const int k0 = dc + ks * 16 + lk;    // e smem offset
                const int kl = ks * 16 + lk;         // w smem offset
                unsigned a[2][4];
                #pragma unroll
                for (int mf = 0; mf < 2; mf++) {
                    int r = wrow * 32 + mf * 16 + lr;
                    a[mf][0] = *(const unsigned*)(e_s + r * ESTR + k0);
                    a[mf][1] = *(const unsigned*)(e_s + (r + 8) * ESTR + k0);
                    a[mf][2] = *(const unsigned*)(e_s + r * ESTR + k0 + 8);
                    a[mf][3] = *(const unsigned*)(e_s + (r + 8) * ESTR + k0 + 8);
                }
                #pragma unroll
                for (int nf = 0; nf < 4; nf++) {
                    int c = wcol * 32 + nf * 8 + lr;
                    unsigned b0 = *(const unsigned*)(wS + c * WSTR + kl);
                    unsigned b1 = *(const unsigned*)(wS + c * WSTR + kl + 8);
                    mma_f16(acc[0][nf], a[0], b0, b1);
                    mma_f16(acc[1][nf], a[1], b0, b1);
                }
            }
        }

        // ---- epilogue: score + running top-2 ----
        #pragma unroll
        for (int mf = 0; mf < 2; mf++)
        #pragma unroll
        for (int rh = 0; rh < 2; rh++) {
            const int slot = mf * 2 + rh;
            float A = A_s[wrow * 32 + mf * 16 + rh * 8 + lr];
            #pragma unroll
            for (int nf = 0; nf < 4; nf++)
            #pragma unroll
            for (int ci = 0; ci < 2; ci++) {
                int code = ct * BM + wcol * 32 + nf * 8 + (lane & 3) * 2 + ci;
                float dot = acc[mf][nf][rh * 2 + ci];
                float s = __fadd_rn(__fadd_rn(A, -2.0f * dot), nw_s[code]);
                if (s < best[slot] || (s == best[slot] && code < bidx[slot])) {
                    sec[slot]  = best[slot];
                    best[slot] = s; bidx[slot] = code;
                } else if (s < sec[slot]) {
                    sec[slot] = s;
                }
            }
        }
    }

    // ---- cross-lane top-2 merge (lanes sharing a row differ in lane&3) ----
    #pragma unroll
    for (int slot = 0; slot < 4; slot++) {
        #pragma unroll
        for (int o = 1; o < 4; o <<= 1) {
            float ob = __shfl_xor_sync(0xffffffffu, best[slot], o);
            float os = __shfl_xor_sync(0xffffffffu, sec[slot], o);
            int   oi = __shfl_xor_sync(0xffffffffu, bidx[slot], o);
            if (ob < best[slot] || (ob == best[slot] && oi < bidx[slot])) {
                sec[slot]  = fminf(best[slot], os);
                best[slot] = ob; bidx[slot] = oi;
            } else {
                sec[slot] = fminf(sec[slot], ob);
            }
        }
    }
    if ((lane & 3) == 0) {
        #pragma unroll
        for (int slot = 0; slot < 4; slot++) {
            int mf = slot >> 1, rh = slot & 1;
            int row = wrow * 32 + mf * 16 + rh * 8 + lr;
            rS[row * 4 + wcol] = best[slot];
            rC[row * 4 + wcol] = sec[slot];
            rI[row * 4 + wcol] = bidx[slot];
        }
    }
    __syncthreads();
    if (t < BM) {
        float fb = rS[t * 4], fs = rC[t * 4];
        int   fi = rI[t * 4];
        #pragma unroll
        for (int j = 1; j < 4; j++) {
            float b = rS[t * 4 + j], c = rC[t * 4 + j];
            int   i = rI[t * 4 + j];
            if (b < fb || (b == fb && i < fi)) {
                fs = fminf(fb, c); fb = b; fi = i;
            } else {
                fs = fminf(fs, b);
            }
        }
        g_idx[rowbase + t] = fi;
        if (fs - fb < RESCUE_THRESH) {
            g_rbest[rowbase + t] = 0xFFFFFFFFFFFFFFFFull;
            int pos = atomicAdd(&g_flagcnt, 1);
            if (pos < NMAX) g_flaglist[pos] = rowbase + t;
        }
    }
}

// ---------------------------------------------------------------------------
// Kernel: exact fp32 rescore of flagged rows, v4: K-split (unchanged).
// ---------------------------------------------------------------------------
__global__ void __launch_bounds__(256)
vq_rescue(const float* __restrict__ e, const float* __restrict__ w, int K) {
    extern __shared__ float rsm[];
    float* e_s = rsm;                   // [RROWS][260]
    float* w_s = e_s + RROWS * 260;     // [32][260]
    float* nwt = w_s + 32 * 260;        // [32]

    const int t    = threadIdx.x;
    const int wid  = t >> 5;
    const int lane = t & 31;
    const int nflag = g_flagcnt;
    const int kbase = (blockIdx.x & (KSLICES - 1)) * (KMAX / KSLICES);

    for (int base = (blockIdx.x / KSLICES) * RROWS; base < nflag;
         base += (gridDim.x / KSLICES) * RROWS) {
        const int s0 = base + wid * 2, s1 = base + wid * 2 + 1;
        const int row0 = (s0 < nflag) ? g_flaglist[s0] : -1;
        const int row1 = (s1 < nflag) ? g_flaglist[s1] : -1;

        if (row0 >= 0) {
            const float4* src = (const float4*)(e + (size_t)row0 * D);
            *(float4*)&e_s[(wid * 2) * 260 + lane * 8]     = src[lane * 2];
            *(float4*)&e_s[(wid * 2) * 260 + lane * 8 + 4] = src[lane * 2 + 1];
        }
        if (row1 >= 0) {
            const float4* src = (const float4*)(e + (size_t)row1 * D);
            *(float4*)&e_s[(wid * 2 + 1) * 260 + lane * 8]     = src[lane * 2];
            *(float4*)&e_s[(wid * 2 + 1) * 260 + lane * 8 + 4] = src[lane * 2 + 1];
        }
        const float A0 = (row0 >= 0) ? g_A[row0] : 0.0f;
        const float A1 = (row1 >= 0) ? g_A[row1] : 0.0f;
        float best0 = FLT_MAX, best1 = FLT_MAX;
        int   bi0 = 0, bi1 = 0;

        for (int cti = 0; cti < (KMAX / KSLICES); cti += 32) {
            const int ct = kbase + cti;
            __syncthreads();
            #pragma unroll
            for (int i = 0; i < 8; i++) {
                int id = t + i * 256;
                int c  = id >> 6;
                int v  = (id & 63) * 4;
                *(float4*)&w_s[c * 260 + v] =
                    __ldg((const float4*)(w + (size_t)(ct + c) * D + v));
            }
            if (t < 32) nwt[t] = g_nw[ct + t];
            __syncthreads();

            const float* wrow = &w_s[lane * 260];
            float a0 = 0.f, a1 = 0.f, a2 = 0.f, a3 = 0.f;
            float c0 = 0.f, c1 = 0.f, c2 = 0.f, c3 = 0.f;
            #pragma unroll
            for (int v = 0; v < D; v += 8) {
                float4 wv0 = *(const float4*)&wrow[v];
                float4 wv1 = *(const float4*)&wrow[v + 4];
                float4 e00 = *(const float4*)&e_s[(wid * 2) * 260 + v];
                float4 e01 = *(const float4*)&e_s[(wid * 2) * 260 + v + 4];
                a0 += e00.x * wv0.x + e01.x * wv1.x;
                a1 += e00.y * wv0.y + e01.y * wv1.y;
                a2 += e00.z * wv0.z + e01.z * wv1.z;
                a3 += e00.w * wv0.w + e01.w * wv1.w;
                float4 e10 = *(const float4*)&e_s[(wid * 2 + 1) * 260 + v];
                float4 e11 = *(const float4*)&e_s[(wid * 2 + 1) * 260 + v + 4];
                c0 += e10.x * wv0.x + e11.x * wv1.x;
                c1 += e10.y * wv0.y + e11.y * wv1.y;
                c2 += e10.z * wv0.z + e11.z * wv1.z;
                c3 += e10.w * wv0.w + e11.w * wv1.w;
            }
            float nv = nwt[lane];
            int code = ct + lane;
            float dot0 = (a0 + a1) + (a2 + a3);
            float dot1 = (c0 + c1) + (c2 + c3);
            float sc0 = __fadd_rn(__fadd_rn(A0, -2.0f * dot0), nv);
            float sc1 = __fadd_rn(__fadd_rn(A1, -2.0f * dot1), nv);
            if (sc0 < best0) { best0 = sc0; bi0 = code; }
            if (sc1 < best1) { best1 = sc1; bi1 = code; }
        }

        #pragma unroll
        for (int o = 16; o; o >>= 1) {
            float ob = __shfl_xor_sync(0xffffffffu, best0, o);
            int   oi = __shfl_xor_sync(0xffffffffu, bi0, o);
            if (ob < best0 || (ob == best0 && oi < bi0)) { best0 = ob; bi0 = oi; }
            float pb = __shfl_xor_sync(0xffffffffu, best1, o);
            int   pi = __shfl_xor_sync(0xffffffffu, bi1, o);
            if (pb < best1 || (pb == best1 && pi < bi1)) { best1 = pb; bi1 = pi; }
        }
        if (lane == 0) {
            if (row0 >= 0) {
                unsigned long long pk =
                    ((unsigned long long)__float_as_uint(best0) << 32) | (unsigned)bi0;
                atomicMin(&g_rbest[row0], pk);
            }
            if (row1 >= 0) {
                unsigned long long pk =
                    ((unsigned long long)__float_as_uint(best1) << 32) | (unsigned)bi1;
                atomicMin(&g_rbest[row1], pk);
            }
        }
        __syncthreads();
    }
}

// ---------------------------------------------------------------------------
// Kernel: resolve flagged rows' indices from g_rbest.
// ---------------------------------------------------------------------------
__global__ void vq_resolve() {
    int i = blockIdx.x * blockDim.x + threadIdx.x;
    if (i < g_flagcnt && i < NMAX) {
        int row = g_flaglist[i];
        g_idx[row] = (int)(unsigned)(g_rbest[row] & 0xFFFFFFFFull);
    }
}

// ---------------------------------------------------------------------------
// Kernel: gather quantized rows, write indices, accumulate loss + counts.
// ---------------------------------------------------------------------------
__global__ void vq_gather_kernel(const float* __restrict__ e,
                                 const float* __restrict__ w,
                                 float* __restrict__ out,
                                 long long out_size, int N) {
    __shared__ double bsum[8];
    const int wl   = threadIdx.x >> 5;
    const int lane = threadIdx.x & 31;
    const int row  = blockIdx.x * 8 + wl;

    float ss = 0.0f;
    int idx = 0;
    if (row < N) {
        idx = g_idx[row];
        const float4* qp = (const float4*)(w + (size_t)idx * D);
        const float4* ep = (const float4*)(e + (size_t)row * D);
        float4*       op = (float4*)(out + (size_t)row * D);
        #pragma unroll
        for (int c = 0; c < 2; c++) {
            int i = lane + c * 32;
            float4 q  = __ldg(&qp[i]);
            float4 ev = ep[i];
            op[i] = q;
            float dx = q.x - ev.x, dy = q.y - ev.y;
            float dz = q.z - ev.z, dw = q.w - ev.w;
            ss += dx * dx + dy * dy + dz * dz + dw * dw;
        }
    }
    #pragma unroll
    for (int o = 16; o; o >>= 1) ss += __shfl_xor_sync(0xffffffffu, ss, o);
    if (lane == 0) {
        bsum[wl] = (double)ss;
        if (row < N) {
            atomicAdd(&g_counts[idx], 1u);
            long long p = (long long)N * D + row;
            if (p < out_size) out[p] = (float)idx;
        }
    }
    __syncthreads();
    if (threadIdx.x == 0) {
        double s = 0.0;
        #pragma unroll
        for (int i = 0; i < 8; i++) s += bsum[i];
        atomicAdd(&g_loss, s);
    }
}

// ---------------------------------------------------------------------------
// Kernel: finalize scalars.
// ---------------------------------------------------------------------------
__global__ void vq_finalize_kernel(float* __restrict__ out, long long out_size,
                                   int N, int K) {
    __shared__ unsigned red[1024];
    int t = threadIdx.x;
    unsigned m = (t < K) ? g_counts[t] : 0u;
    red[t] = m;
    __syncthreads();
    #pragma unroll
    for (int s = 512; s; s >>= 1) {
        if (t < s) { unsigned o = red[t + s]; if (o > red[t]) red[t] = o; }
        __syncthreads();
    }
    if (t == 0) {
        long long base = (long long)N * D + N;
        if (base < out_size)
            out[base] = (float)(g_loss / ((double)N * (double)D));
        if (base + 1 < out_size)
            out[base + 1] = (float)red[0] / (float)N;
    }
}

// ---------------------------------------------------------------------------
extern "C" void kernel_launch(void* const* d_in, const int* in_sizes, int n_in,
                              void* d_out, int out_size) {
    const float* e = (const float*)d_in[0];
    const float* w = (const float*)d_in[1];
    float* out = (float*)d_out;

    int N = in_sizes[0] / D;
    int K = in_sizes[1] / D;
    if (N > NMAX) N = NMAX;
    if (K > KMAX) K = KMAX;
    long long osz = (long long)out_size;

    cudaFuncSetAttribute(vq_argmin_mma,
                         cudaFuncAttributeMaxDynamicSharedMemorySize, SMEM_BYTES);
    cudaFuncSetAttribute(vq_rescue,
                         cudaFuncAttributeMaxDynamicSharedMemorySize, RS_BYTES);

    vq_prep_e<<<(N * 32 + 255) / 256, 256>>>(e, N);
    vq_prep_w<<<(K * 32 + 255) / 256, 256>>>(w, K);
    vq_argmin_mma<<<N / BM, NTHR, SMEM_BYTES>>>(K);
    vq_rescue<<<1024, 256, RS_BYTES>>>(e, w, K);
    vq_resolve<<<NMAX / 256, 256>>>();
    vq_gather_kernel<<<(N + 7) / 8, 256>>>(e, w, out, osz, N);
    vq_finalize_kernel<<<1, 1024>>>(out, osz, N, K);
}